// round 6
// baseline (speedup 1.0000x reference)
#include <cuda_runtime.h>
#include <cstdint>
#include <cstddef>

#define ENCD 1024
#define NB   32
#define NS   2048
#define MTOT (NB*NS)   // 65536

// ---- scratch (no allocations allowed) ----
__device__ float g_q[NB*ENCD];      // dec@w2 + b1 + b2
__device__ float g_scores[NB*NS];   // pre-softmax scores (atomic accum)
__device__ float g_attn[NB*NS];     // softmax weights

// ============================================================
// K0: zero scores + output (output is atomically accumulated)
// ============================================================
__global__ void k_zero(float* __restrict__ out) {
    int i = blockIdx.x * blockDim.x + threadIdx.x;
    if (i < NB*NS)  g_scores[i] = 0.f;
    if (i < NB*ENCD) out[i] = 0.f;
}

// ============================================================
// K1: g_q[b,e] = sum_d dec[b,d]*w2[d,e] + b1[e] + b2[e]
// grid (32, 8), block 128
// ============================================================
__global__ void k_query(const float* __restrict__ dec, const float* __restrict__ w2,
                        const float* __restrict__ b1, const float* __restrict__ b2) {
    __shared__ float sdec[ENCD];
    const int b = blockIdx.x;
    const int e = blockIdx.y * 128 + threadIdx.x;
    for (int d = threadIdx.x; d < ENCD; d += 128) sdec[d] = dec[b*ENCD + d];
    __syncthreads();
    float acc = 0.f;
#pragma unroll 8
    for (int d = 0; d < ENCD; d++) acc += sdec[d] * w2[(size_t)d*ENCD + e];
    g_q[b*ENCD + e] = acc + b1[e] + b2[e];
}

// ============================================================
// K2: fused GEMM (enc @ w1) + tanh + v-dot -> partial scores
//     tf32 mma.sync m16n8k8, 128x128x16 tiles, 2-stage cp.async
// ============================================================
#define BM 128
#define BN 128
#define BK 16
#define ASTRIDE (BK + 4)    // 20 floats: banks (4g+t) -> conflict free
#define BSTRIDE (BN + 8)    // 136 floats: banks (8t+g) -> conflict free

__device__ __forceinline__ void mma_tf32(float* d, const uint32_t* a, const uint32_t* b) {
    asm volatile(
        "mma.sync.aligned.m16n8k8.row.col.f32.tf32.tf32.f32 "
        "{%0,%1,%2,%3}, {%4,%5,%6,%7}, {%8,%9}, {%0,%1,%2,%3};\n"
        : "+f"(d[0]), "+f"(d[1]), "+f"(d[2]), "+f"(d[3])
        : "r"(a[0]), "r"(a[1]), "r"(a[2]), "r"(a[3]), "r"(b[0]), "r"(b[1]));
}

__global__ __launch_bounds__(256, 2)
void k_scores(const float* __restrict__ A, const float* __restrict__ W,
              const float* __restrict__ v) {
    __shared__ float As[2][BM][ASTRIDE];
    __shared__ float Bs[2][BK][BSTRIDE];
    __shared__ float sq[BN];
    __shared__ float sv[BN];

    const int n0   = blockIdx.x * BN;   // n-tile fastest -> A reused via L2
    const int m0   = blockIdx.y * BM;
    const int b    = m0 >> 11;          // 2048 rows per batch, BM divides 2048
    const int tid  = threadIdx.x;
    const int wid  = tid >> 5;
    const int lane = tid & 31;
    const int g    = lane >> 2;         // 0..7
    const int t4   = lane & 3;          // 0..3
    const int warpM = wid >> 2;         // 0..1 (64 rows each)
    const int warpN = wid & 3;          // 0..3 (32 cols each)

    if (tid < BN) {
        sq[tid] = g_q[b*ENCD + n0 + tid];
        sv[tid] = v[n0 + tid];
    }

    float acc[4][4][4];
#pragma unroll
    for (int i = 0; i < 4; i++)
#pragma unroll
        for (int j = 0; j < 4; j++)
#pragma unroll
            for (int r = 0; r < 4; r++) acc[i][j][r] = 0.f;

    // A tile: 128 rows x 16 floats = 512 x 16B chunks; B tile: 16 rows x 128 floats = 512 chunks
    auto loadA = [&](int kt, int buf) {
#pragma unroll
        for (int q = 0; q < 2; q++) {
            int c = tid*2 + q;
            int row = c >> 2, cc = (c & 3) * 4;
            uint32_t dst = (uint32_t)__cvta_generic_to_shared(&As[buf][row][cc]);
            const float* src = A + (size_t)(m0 + row)*ENCD + kt*BK + cc;
            asm volatile("cp.async.cg.shared.global [%0], [%1], 16;\n" :: "r"(dst), "l"(src));
        }
    };
    auto loadB = [&](int kt, int buf) {
#pragma unroll
        for (int q = 0; q < 2; q++) {
            int c = tid*2 + q;
            int row = c >> 5, cc = (c & 31) * 4;
            uint32_t dst = (uint32_t)__cvta_generic_to_shared(&Bs[buf][row][cc]);
            const float* src = W + (size_t)(kt*BK + row)*ENCD + n0 + cc;
            asm volatile("cp.async.cg.shared.global [%0], [%1], 16;\n" :: "r"(dst), "l"(src));
        }
    };

    const int NK = ENCD / BK;  // 64
    loadA(0, 0); loadB(0, 0);
    asm volatile("cp.async.commit_group;\n" ::: "memory");

    for (int kt = 0; kt < NK; kt++) {
        const int buf = kt & 1;
        if (kt + 1 < NK) { loadA(kt + 1, buf ^ 1); loadB(kt + 1, buf ^ 1); }
        asm volatile("cp.async.commit_group;\n" ::: "memory");
        asm volatile("cp.async.wait_group 1;\n" ::: "memory");
        __syncthreads();

#pragma unroll
        for (int ks = 0; ks < BK/8; ks++) {
            uint32_t af[4][4], bf[4][2];
#pragma unroll
            for (int im = 0; im < 4; im++) {
                int r = warpM*64 + im*16 + g;
                af[im][0] = __float_as_uint(As[buf][r    ][ks*8 + t4    ]);
                af[im][1] = __float_as_uint(As[buf][r + 8][ks*8 + t4    ]);
                af[im][2] = __float_as_uint(As[buf][r    ][ks*8 + t4 + 4]);
                af[im][3] = __float_as_uint(As[buf][r + 8][ks*8 + t4 + 4]);
            }
#pragma unroll
            for (int in = 0; in < 4; in++) {
                int c = warpN*32 + in*8 + g;
                bf[in][0] = __float_as_uint(Bs[buf][ks*8 + t4    ][c]);
                bf[in][1] = __float_as_uint(Bs[buf][ks*8 + t4 + 4][c]);
            }
#pragma unroll
            for (int im = 0; im < 4; im++)
#pragma unroll
                for (int in = 0; in < 4; in++)
                    mma_tf32(acc[im][in], af[im], bf[in]);
        }
        __syncthreads();
    }

    // epilogue: scores_partial(row) += sum_cols tanh(acc + q[col]) * v[col]
    float part[8];
#pragma unroll
    for (int i = 0; i < 8; i++) part[i] = 0.f;
#pragma unroll
    for (int im = 0; im < 4; im++) {
#pragma unroll
        for (int in = 0; in < 4; in++) {
            int c = warpN*32 + in*8 + 2*t4;
            float q0 = sq[c], q1 = sq[c + 1];
            float v0 = sv[c], v1 = sv[c + 1];
            part[2*im    ] += tanhf(acc[im][in][0] + q0) * v0
                            + tanhf(acc[im][in][1] + q1) * v1;
            part[2*im + 1] += tanhf(acc[im][in][2] + q0) * v0
                            + tanhf(acc[im][in][3] + q1) * v1;
        }
    }
    // reduce across the 4 lanes (t4) that share the same rows
#pragma unroll
    for (int i = 0; i < 8; i++) {
        part[i] += __shfl_xor_sync(0xffffffff, part[i], 1);
        part[i] += __shfl_xor_sync(0xffffffff, part[i], 2);
    }
    if (t4 == 0) {
#pragma unroll
        for (int im = 0; im < 4; im++) {
            int r = m0 + warpM*64 + im*16 + g;
            atomicAdd(&g_scores[r],     part[2*im]);
            atomicAdd(&g_scores[r + 8], part[2*im + 1]);
        }
    }
}

// ============================================================
// K3: per-batch softmax over S=2048
// ============================================================
__global__ void k_softmax() {
    __shared__ float red[256];
    const int b = blockIdx.x, tid = threadIdx.x;
    const float* sc = &g_scores[b*NS];

    float mx = -1e30f;
    for (int i = tid; i < NS; i += 256) mx = fmaxf(mx, sc[i]);
    red[tid] = mx; __syncthreads();
    for (int s = 128; s > 0; s >>= 1) { if (tid < s) red[tid] = fmaxf(red[tid], red[tid+s]); __syncthreads(); }
    mx = red[0]; __syncthreads();

    float sum = 0.f;
    for (int i = tid; i < NS; i += 256) {
        float e = expf(sc[i] - mx);
        g_attn[b*NS + i] = e;
        sum += e;
    }
    red[tid] = sum; __syncthreads();
    for (int s = 128; s > 0; s >>= 1) { if (tid < s) red[tid] += red[tid+s]; __syncthreads(); }
    float inv = 1.f / red[0];
    for (int i = tid; i < NS; i += 256) g_attn[b*NS + i] *= inv;
}

// ============================================================
// K4: context[b,e] = sum_s attn[b,s] * enc[b,s,e]
// grid (32, 4 e-chunks, 8 s-chunks), block 256; atomic combine over s-chunks
// ============================================================
__global__ void k_context(const float* __restrict__ enc, float* __restrict__ out) {
    __shared__ float sa[256];
    const int b   = blockIdx.x;
    const int ec  = blockIdx.y;
    const int scb = blockIdx.z;
    const int tid = threadIdx.x;

    sa[tid] = g_attn[b*NS + scb*256 + tid];
    __syncthreads();

    const int e = ec*256 + tid;
    const float* ep = enc + ((size_t)b*NS + (size_t)scb*256) * ENCD + e;
    float acc = 0.f;
#pragma unroll 4
    for (int s = 0; s < 256; s++) acc += sa[s] * ep[(size_t)s * ENCD];
    atomicAdd(&out[b*ENCD + e], acc);
}

// ============================================================
extern "C" void kernel_launch(void* const* d_in, const int* in_sizes, int n_in,
                              void* d_out, int out_size) {
    const float* enc = (const float*)d_in[0];  // [32,2048,1024]
    const float* dec = (const float*)d_in[1];  // [32,1,1024]
    const float* w1  = (const float*)d_in[2];  // [1024,1024]
    const float* b1  = (const float*)d_in[3];  // [1024]
    const float* w2  = (const float*)d_in[4];  // [1024,1024]
    const float* b2  = (const float*)d_in[5];  // [1024]
    const float* v   = (const float*)d_in[6];  // [1024] (bv is softmax-invariant, dropped)
    float* out = (float*)d_out;                // [32,1024]

    k_zero<<<256, 256>>>(out);
    k_query<<<dim3(32, 8), 128>>>(dec, w2, b1, b2);
    k_scores<<<dim3(ENCD/BN, MTOT/BM), 256>>>(enc, w1, v);
    k_softmax<<<32, 256>>>();
    k_context<<<dim3(32, 4, 8), 256>>>(enc, out);
}

// round 13
// speedup vs baseline: 1.5072x; 1.5072x over previous
#include <cuda_runtime.h>
#include <cuda_fp16.h>
#include <cstdint>
#include <cstddef>

#define ENCD 1024
#define NB   32
#define NS   2048
#define MTOT (NB*NS)   // 65536

// ---- scratch (module globals; no runtime allocations) ----
__device__ float  g_q[NB*ENCD];                      // dec@w2 + b1 + b2
__device__ float  g_scores[NB*NS];                   // pre-softmax scores (atomic accum)
__device__ float  g_attn[NB*NS];                     // softmax weights
__device__ __align__(16) __half g_w1t_h[ENCD*ENCD]; // w1 transposed fp16: [e][d], d contiguous
__device__ __align__(16) __half g_enc_h[(size_t)MTOT*ENCD]; // enc in fp16 (128 MB)

// ============================================================
// K0: zero scores + output (both atomically accumulated)
// ============================================================
__global__ void k_zero(float* __restrict__ out) {
    int i = blockIdx.x * blockDim.x + threadIdx.x;
    if (i < NB*NS)  g_scores[i] = 0.f;
    if (i < NB*ENCD) out[i] = 0.f;
}

// ============================================================
// K-C: convert enc fp32 -> fp16 (4 floats / thread)
// grid 65536 x 256
// ============================================================
__global__ void k_convert(const float* __restrict__ enc) {
    size_t i = ((size_t)blockIdx.x * 256 + threadIdx.x) * 4;
    float4 f = *(const float4*)(enc + i);
    __half2 h0 = __floats2half2_rn(f.x, f.y);
    __half2 h1 = __floats2half2_rn(f.z, f.w);
    __half2* dst = (__half2*)(g_enc_h + i);
    dst[0] = h0;
    dst[1] = h1;
}

// ============================================================
// K-T: transpose w1 -> g_w1t_h  (g_w1t_h[e,d] = (half)w1[d,e])
// ============================================================
__global__ void k_transpose(const float* __restrict__ w) {
    __shared__ float t[32][33];
    int bx = blockIdx.x * 32, by = blockIdx.y * 32;
    int tx = threadIdx.x;
    for (int i = threadIdx.y; i < 32; i += 8)
        t[i][tx] = w[(size_t)(by + i) * ENCD + bx + tx];
    __syncthreads();
    for (int i = threadIdx.y; i < 32; i += 8)
        g_w1t_h[(size_t)(bx + i) * ENCD + by + tx] = __float2half(t[tx][i]);
}

// ============================================================
// K1: g_q[b,e] = dec[b]@w2 + b1 + b2   (fp32, tiny)
// ============================================================
__global__ void k_query(const float* __restrict__ dec, const float* __restrict__ w2,
                        const float* __restrict__ b1, const float* __restrict__ b2) {
    __shared__ float sdec[ENCD];
    const int b = blockIdx.x;
    const int e = blockIdx.y * 128 + threadIdx.x;
    for (int d = threadIdx.x; d < ENCD; d += 128) sdec[d] = dec[b*ENCD + d];
    __syncthreads();
    float acc = 0.f;
#pragma unroll 8
    for (int d = 0; d < ENCD; d++) acc += sdec[d] * w2[(size_t)d*ENCD + e];
    g_q[b*ENCD + e] = acc + b1[e] + b2[e];
}

// ============================================================
// K2: fp16 mma.sync GEMM (enc_h @ w1t_h^T) + tanh + v-dot -> scores
//     m16n8k16, 128x128x32 tiles, 2-stage cp.async
// ============================================================
#define BM 128
#define BN 128
#define BK 32
#define AS 40            // smem row stride in halves (80 B): banks (20g+t4) all-distinct
#define NKT (ENCD/BK)    // 32

#define CP16(dst, src) \
    asm volatile("cp.async.cg.shared.global [%0], [%1], 16;\n" :: "r"(dst), "l"(src))
#define CPC()  asm volatile("cp.async.commit_group;\n" ::: "memory")
#define CPW1() asm volatile("cp.async.wait_group 1;\n" ::: "memory")

__device__ __forceinline__ uint32_t smem_u32(const void* p) {
    uint32_t a;
    asm("{ .reg .u64 t; cvta.to.shared.u64 t, %1; cvt.u32.u64 %0, t; }" : "=r"(a) : "l"(p));
    return a;
}

__device__ __forceinline__ void mma_f16(float* d, const uint32_t* a, const uint32_t* b) {
    asm volatile(
        "mma.sync.aligned.m16n8k16.row.col.f32.f16.f16.f32 "
        "{%0,%1,%2,%3}, {%4,%5,%6,%7}, {%8,%9}, {%0,%1,%2,%3};\n"
        : "+f"(d[0]), "+f"(d[1]), "+f"(d[2]), "+f"(d[3])
        : "r"(a[0]), "r"(a[1]), "r"(a[2]), "r"(a[3]), "r"(b[0]), "r"(b[1]));
}

__global__ __launch_bounds__(256, 2)
void k_scores_h(const float* __restrict__ v) {
    __shared__ __half Asm[2][BM][AS];
    __shared__ __half Bsm[2][BN][AS];
    __shared__ float sq[BN];
    __shared__ float sv[BN];

    const int n0   = blockIdx.x * BN;   // n-tile fastest -> A reuse via L2
    const int m0   = blockIdx.y * BM;
    const int b    = m0 >> 11;
    const int tid  = threadIdx.x;
    const int wid  = tid >> 5;
    const int lane = tid & 31;
    const int g    = lane >> 2;         // 0..7
    const int t4   = lane & 3;          // 0..3
    const int warpM = wid >> 2;         // 0..1 (64 rows)
    const int warpN = wid & 3;          // 0..3 (32 cols)

    if (tid < BN) {
        sq[tid] = g_q[b*ENCD + n0 + tid];
        sv[tid] = v[n0 + tid];
    }

    float acc[4][4][4];
#pragma unroll
    for (int i = 0; i < 4; i++)
#pragma unroll
        for (int j = 0; j < 4; j++)
#pragma unroll
            for (int r = 0; r < 4; r++) acc[i][j][r] = 0.f;

    const uint32_t sA = smem_u32(&Asm[0][0][0]);
    const uint32_t sB = smem_u32(&Bsm[0][0][0]);

    // per tile: 128 rows x 32 halves = 64B/row = 4 x 16B chunks -> 512 chunks
    auto ldA = [&](int kt, int st) {
        const __half* gp = g_enc_h + (size_t)m0*ENCD + kt*BK;
        uint32_t base = sA + (uint32_t)st * (BM*AS*2);
#pragma unroll
        for (int q = 0; q < 2; q++) {
            int c = tid*2 + q;
            int row = c >> 2, j = c & 3;
            CP16(base + row*(AS*2) + j*16, gp + (size_t)row*ENCD + j*8);
        }
    };
    auto ldB = [&](int kt, int st) {
        const __half* gp = g_w1t_h + (size_t)n0*ENCD + kt*BK;
        uint32_t base = sB + (uint32_t)st * (BN*AS*2);
#pragma unroll
        for (int q = 0; q < 2; q++) {
            int c = tid*2 + q;
            int row = c >> 2, j = c & 3;
            CP16(base + row*(AS*2) + j*16, gp + (size_t)row*ENCD + j*8);
        }
    };

    ldA(0, 0); ldB(0, 0); CPC();

    for (int kt = 0; kt < NKT; kt++) {
        const int buf = kt & 1;
        if (kt + 1 < NKT) { ldA(kt + 1, buf ^ 1); ldB(kt + 1, buf ^ 1); }
        CPC();
        CPW1();
        __syncthreads();

#pragma unroll
        for (int ks = 0; ks < BK/16; ks++) {
            const int ko = ks * 16;
            uint32_t af[4][4], bf[4][2];
#pragma unroll
            for (int im = 0; im < 4; im++) {
                int r = warpM*64 + im*16 + g;
                af[im][0] = *(const uint32_t*)&Asm[buf][r    ][ko + 2*t4    ];
                af[im][1] = *(const uint32_t*)&Asm[buf][r + 8][ko + 2*t4    ];
                af[im][2] = *(const uint32_t*)&Asm[buf][r    ][ko + 2*t4 + 8];
                af[im][3] = *(const uint32_t*)&Asm[buf][r + 8][ko + 2*t4 + 8];
            }
#pragma unroll
            for (int in = 0; in < 4; in++) {
                int n = warpN*32 + in*8 + g;
                bf[in][0] = *(const uint32_t*)&Bsm[buf][n][ko + 2*t4    ];
                bf[in][1] = *(const uint32_t*)&Bsm[buf][n][ko + 2*t4 + 8];
            }
#pragma unroll
            for (int im = 0; im < 4; im++)
#pragma unroll
                for (int in = 0; in < 4; in++)
                    mma_f16(acc[im][in], af[im], bf[in]);
        }
        __syncthreads();
    }

    // epilogue: scores(row) += sum_cols tanh(acc + q[col]) * v[col]
    float part[8];
#pragma unroll
    for (int i = 0; i < 8; i++) part[i] = 0.f;
#pragma unroll
    for (int im = 0; im < 4; im++) {
#pragma unroll
        for (int in = 0; in < 4; in++) {
            int c = warpN*32 + in*8 + 2*t4;
            float q0 = sq[c], q1 = sq[c + 1];
            float v0 = sv[c], v1 = sv[c + 1];
            part[2*im    ] += tanhf(acc[im][in][0] + q0) * v0
                            + tanhf(acc[im][in][1] + q1) * v1;
            part[2*im + 1] += tanhf(acc[im][in][2] + q0) * v0
                            + tanhf(acc[im][in][3] + q1) * v1;
        }
    }
#pragma unroll
    for (int i = 0; i < 8; i++) {
        part[i] += __shfl_xor_sync(0xffffffff, part[i], 1);
        part[i] += __shfl_xor_sync(0xffffffff, part[i], 2);
    }
    if (t4 == 0) {
#pragma unroll
        for (int im = 0; im < 4; im++) {
            int r = m0 + warpM*64 + im*16 + g;
            atomicAdd(&g_scores[r],     part[2*im]);
            atomicAdd(&g_scores[r + 8], part[2*im + 1]);
        }
    }
}

// ============================================================
// K3: per-batch softmax over S=2048
// ============================================================
__global__ void k_softmax() {
    __shared__ float red[256];
    const int b = blockIdx.x, tid = threadIdx.x;
    const float* sc = &g_scores[b*NS];

    float mx = -1e30f;
    for (int i = tid; i < NS; i += 256) mx = fmaxf(mx, sc[i]);
    red[tid] = mx; __syncthreads();
    for (int s = 128; s > 0; s >>= 1) { if (tid < s) red[tid] = fmaxf(red[tid], red[tid+s]); __syncthreads(); }
    mx = red[0]; __syncthreads();

    float sum = 0.f;
    for (int i = tid; i < NS; i += 256) {
        float e = expf(sc[i] - mx);
        g_attn[b*NS + i] = e;
        sum += e;
    }
    red[tid] = sum; __syncthreads();
    for (int s = 128; s > 0; s >>= 1) { if (tid < s) red[tid] += red[tid+s]; __syncthreads(); }
    float inv = 1.f / red[0];
    for (int i = tid; i < NS; i += 256) g_attn[b*NS + i] *= inv;
}

// ============================================================
// K4: context[b,e] = sum_s attn[b,s] * enc_h[b,s,e]  (fp16 enc, half DRAM)
// grid (32, 4, 8), block 256; atomic combine over s-chunks
// ============================================================
__global__ void k_context(float* __restrict__ out) {
    __shared__ float sa[256];
    const int b   = blockIdx.x;
    const int ec  = blockIdx.y;
    const int scb = blockIdx.z;
    const int tid = threadIdx.x;

    sa[tid] = g_attn[b*NS + scb*256 + tid];
    __syncthreads();

    const int e = ec*256 + tid;
    const __half* ep = g_enc_h + ((size_t)b*NS + (size_t)scb*256) * ENCD + e;
    float acc = 0.f;
#pragma unroll 4
    for (int s = 0; s < 256; s++) acc += sa[s] * __half2float(ep[(size_t)s * ENCD]);
    atomicAdd(&out[b*ENCD + e], acc);
}

// ============================================================
extern "C" void kernel_launch(void* const* d_in, const int* in_sizes, int n_in,
                              void* d_out, int out_size) {
    const float* enc = (const float*)d_in[0];  // [32,2048,1024]
    const float* dec = (const float*)d_in[1];  // [32,1,1024]
    const float* w1  = (const float*)d_in[2];  // [1024,1024]
    const float* b1  = (const float*)d_in[3];  // [1024]
    const float* w2  = (const float*)d_in[4];  // [1024,1024]
    const float* b2  = (const float*)d_in[5];  // [1024]
    const float* v   = (const float*)d_in[6];  // [1024] (bv softmax-invariant, dropped)
    float* out = (float*)d_out;                // [32,1024]

    k_zero<<<256, 256>>>(out);
    k_convert<<<65536, 256>>>(enc);
    k_transpose<<<dim3(32, 32), dim3(32, 8)>>>(w1);
    k_query<<<dim3(32, 8), 128>>>(dec, w2, b1, b2);
    k_scores_h<<<dim3(ENCD/BN, MTOT/BM), 256>>>(v);
    k_softmax<<<32, 256>>>();
    k_context<<<dim3(32, 4, 8), 256>>>(out);
}